// round 11
// baseline (speedup 1.0000x reference)
#include <cuda_runtime.h>
#include <cuda_bf16.h>
#include <cstdint>

// Problem constants
#define BATCH 4
#define SEQ   2048
#define EMB   1024          // E == D
#define NHEAD 16
#define HDIM  64
#define MROWS (BATCH * SEQ) // 8192

// ---------------- scratch (static device globals; no allocation) ------------
__device__ __nv_bfloat16 g_inh[MROWS * EMB];
__device__ __nv_bfloat16 g_inl[MROWS * EMB];
__device__ __nv_bfloat16 g_qph[MROWS * EMB];
__device__ __nv_bfloat16 g_qpl[MROWS * EMB];
__device__ __nv_bfloat16 g_kph[MROWS * EMB];
__device__ __nv_bfloat16 g_kpl[MROWS * EMB];
__device__ __nv_bfloat16 g_vph[MROWS * EMB];
__device__ __nv_bfloat16 g_vpl[MROWS * EMB];
__device__ __nv_bfloat16 g_atth[MROWS * EMB];
__device__ __nv_bfloat16 g_attl[MROWS * EMB];
__device__ __nv_bfloat16 g_wth[4][EMB * EMB];  // transposed [N][K] hi
__device__ __nv_bfloat16 g_wtl[4][EMB * EMB];  // transposed [N][K] lo

// ---------------- helpers ----------------------------------------------------
__device__ __forceinline__ void mma_bf16(float& d0, float& d1, float& d2, float& d3,
                                         uint32_t a0, uint32_t a1, uint32_t a2, uint32_t a3,
                                         uint32_t b0, uint32_t b1)
{
    asm volatile(
        "mma.sync.aligned.m16n8k16.row.col.f32.bf16.bf16.f32 "
        "{%0,%1,%2,%3}, {%4,%5,%6,%7}, {%8,%9}, {%0,%1,%2,%3};\n"
        : "+f"(d0), "+f"(d1), "+f"(d2), "+f"(d3)
        : "r"(a0), "r"(a1), "r"(a2), "r"(a3), "r"(b0), "r"(b1));
}

__device__ __forceinline__ void split_bf16(float a, __nv_bfloat16& hi, __nv_bfloat16& lo)
{
    hi = __float2bfloat16(a);
    lo = __float2bfloat16(a - __bfloat162float(hi));
}

__device__ __forceinline__ uint32_t pack_bf16(float x, float y)
{
    __nv_bfloat162 t;
    t.x = __float2bfloat16(x);
    t.y = __float2bfloat16(y);
    return *(uint32_t*)&t;
}

__device__ __forceinline__ uint32_t pack_bf16_lo(float x, float y, uint32_t hi)
{
    __nv_bfloat162 h = *(__nv_bfloat162*)&hi;
    __nv_bfloat162 t;
    t.x = __float2bfloat16(x - __bfloat162float(h.x));
    t.y = __float2bfloat16(y - __bfloat162float(h.y));
    return *(uint32_t*)&t;
}

__device__ __forceinline__ uint32_t smaddr(const void* p)
{
    return (uint32_t)__cvta_generic_to_shared(p);
}

__device__ __forceinline__ void ldsm_x4(uint32_t& r0, uint32_t& r1, uint32_t& r2, uint32_t& r3,
                                        uint32_t addr)
{
    asm volatile("ldmatrix.sync.aligned.m8n8.x4.shared.b16 {%0,%1,%2,%3}, [%4];"
                 : "=r"(r0), "=r"(r1), "=r"(r2), "=r"(r3) : "r"(addr));
}

__device__ __forceinline__ void cp16(uint32_t dst, const void* src)
{
    asm volatile("cp.async.cg.shared.global [%0], [%1], 16;" :: "r"(dst), "l"(src));
}
__device__ __forceinline__ void cp_commit()
{
    asm volatile("cp.async.commit_group;");
}
template<int N>
__device__ __forceinline__ void cp_wait()
{
    asm volatile("cp.async.wait_group %0;" :: "n"(N));
}

// ============================================================================
// Pre-pass 1: split fp32 activation -> hi/lo bf16 (same layout)
// ============================================================================
__global__ __launch_bounds__(256)
void split_kernel(const float* __restrict__ X,
                  __nv_bfloat16* __restrict__ Xh,
                  __nv_bfloat16* __restrict__ Xl)
{
    const int i = (blockIdx.x * 256 + threadIdx.x) * 4;
    float4 v = *(const float4*)(X + i);
    __nv_bfloat16 h0, l0, h1, l1, h2, l2, h3, l3;
    split_bf16(v.x, h0, l0); split_bf16(v.y, h1, l1);
    split_bf16(v.z, h2, l2); split_bf16(v.w, h3, l3);
    *(__nv_bfloat162*)(Xh + i)     = __nv_bfloat162(h0, h1);
    *(__nv_bfloat162*)(Xh + i + 2) = __nv_bfloat162(h2, h3);
    *(__nv_bfloat162*)(Xl + i)     = __nv_bfloat162(l0, l1);
    *(__nv_bfloat162*)(Xl + i + 2) = __nv_bfloat162(l2, l3);
}

// ============================================================================
// Pre-pass 2: weight W[K][N] fp32 -> Wt hi/lo bf16 [N][K] (transposed)
// ============================================================================
__global__ __launch_bounds__(256)
void wsplit_kernel(const float* __restrict__ W,
                   __nv_bfloat16* __restrict__ Wth,
                   __nv_bfloat16* __restrict__ Wtl)
{
    __shared__ float tile[32][33];
    const int n0 = blockIdx.x * 32;
    const int k0 = blockIdx.y * 32;
    const int tx = threadIdx.x;     // 0..31
    const int ty = threadIdx.y;     // 0..7
#pragma unroll
    for (int j = 0; j < 4; j++)
        tile[ty + 8 * j][tx] = W[(size_t)(k0 + ty + 8 * j) * EMB + n0 + tx];
    __syncthreads();
#pragma unroll
    for (int j = 0; j < 4; j++) {
        float v = tile[tx][ty + 8 * j];
        __nv_bfloat16 h, l;
        split_bf16(v, h, l);
        Wth[(size_t)(n0 + ty + 8 * j) * EMB + k0 + tx] = h;
        Wtl[(size_t)(n0 + ty + 8 * j) * EMB + k0 + tx] = l;
    }
}

// ============================================================================
// Tensor-core GEMM: C[M,N] = A[M,K] @ Wt[N,K]^T + bias  (bf16x3, ldmatrix)
// 3-stage cp.async pipeline, BK=16, one __syncthreads per k-tile.
// ============================================================================
#define KP3     24                      // bf16 row stride (48B): conflict-free
#define STG_BF  (4 * 128 * KP3)         // bf16 per stage (12288)
#define GEMM_SMEM (3 * STG_BF * 2)      // 73728 bytes

template<bool SPLIT_OUT>
__global__ __launch_bounds__(256, 2)
void gemm_hl_kernel(const __nv_bfloat16* __restrict__ Ah,
                    const __nv_bfloat16* __restrict__ Al,
                    const __nv_bfloat16* __restrict__ Bth,
                    const __nv_bfloat16* __restrict__ Btl,
                    const float* __restrict__ bias,
                    float* __restrict__ Cf,
                    __nv_bfloat16* __restrict__ Ch,
                    __nv_bfloat16* __restrict__ Cl)
{
    extern __shared__ __nv_bfloat16 sm2[];

    const int tid  = threadIdx.x;
    const int warp = tid >> 5;
    const int lane = tid & 31;
    const int wm   = warp >> 2;   // 0..1
    const int wn   = warp & 3;    // 0..3

    const int ldRow = tid >> 1;          // 0..127
    const int ldK   = (tid & 1) * 8;     // 0 or 8

    const __nv_bfloat16* Ah_p = Ah  + (size_t)(blockIdx.y * 128 + ldRow) * EMB + ldK;
    const __nv_bfloat16* Al_p = Al  + (size_t)(blockIdx.y * 128 + ldRow) * EMB + ldK;
    const __nv_bfloat16* Bh_p = Bth + (size_t)(blockIdx.x * 128 + ldRow) * EMB + ldK;
    const __nv_bfloat16* Bl_p = Btl + (size_t)(blockIdx.x * 128 + ldRow) * EMB + ldK;

    const uint32_t smBase = smaddr(sm2);
    const uint32_t ldOff  = (uint32_t)(ldRow * KP3 + ldK) * 2;

    float acc[4][4][4];
#pragma unroll
    for (int i = 0; i < 4; i++)
#pragma unroll
        for (int j = 0; j < 4; j++)
#pragma unroll
            for (int c = 0; c < 4; c++) acc[i][j][c] = 0.0f;

    // pipeline: load stage s for k-tile t
    auto load_stage = [&](int s, int k0) {
        const uint32_t b = smBase + (uint32_t)s * (STG_BF * 2) + ldOff;
        cp16(b,                    Ah_p + k0);
        cp16(b + 128 * KP3 * 2,    Al_p + k0);
        cp16(b + 2 * 128 * KP3 * 2, Bh_p + k0);
        cp16(b + 3 * 128 * KP3 * 2, Bl_p + k0);
        cp_commit();
    };

    load_stage(0, 0);
    load_stage(1, 16);

    const int T = EMB / 16;   // 64
    int s = 0;
    for (int t = 0; t < T; t++) {
        cp_wait<1>();
        __syncthreads();
        if (t + 2 < T) {
            int ns = s + 2; if (ns >= 3) ns -= 3;
            load_stage(ns, (t + 2) * 16);
        }

        const __nv_bfloat16* As_h = sm2 + s * STG_BF;
        const __nv_bfloat16* As_l = As_h + 128 * KP3;
        const __nv_bfloat16* Bs_h = As_h + 2 * 128 * KP3;
        const __nv_bfloat16* Bs_l = As_h + 3 * 128 * KP3;

        // B fragments
        uint32_t bh[4][2], bl[4][2];
#pragma unroll
        for (int p = 0; p < 2; p++) {
            const int row = wn * 32 + p * 16 + (lane & 7) + ((lane >> 4) & 1) * 8;
            const int kc  = ((lane >> 3) & 1) * 8;
            ldsm_x4(bh[2*p][0], bh[2*p][1], bh[2*p+1][0], bh[2*p+1][1],
                    smaddr(&Bs_h[row * KP3 + kc]));
            ldsm_x4(bl[2*p][0], bl[2*p][1], bl[2*p+1][0], bl[2*p+1][1],
                    smaddr(&Bs_l[row * KP3 + kc]));
        }
#pragma unroll
        for (int mi = 0; mi < 4; mi++) {
            const int r  = wm * 64 + mi * 16 + (lane & 15);
            const int kc = ((lane >> 4) & 1) * 8;
            uint32_t ah0, ah1, ah2, ah3, al0, al1, al2, al3;
            ldsm_x4(ah0, ah1, ah2, ah3, smaddr(&As_h[r * KP3 + kc]));
            ldsm_x4(al0, al1, al2, al3, smaddr(&As_l[r * KP3 + kc]));
#pragma unroll
            for (int ni = 0; ni < 4; ni++) {
                float* d = acc[mi][ni];
                mma_bf16(d[0], d[1], d[2], d[3], ah0, ah1, ah2, ah3, bh[ni][0], bh[ni][1]);
                mma_bf16(d[0], d[1], d[2], d[3], ah0, ah1, ah2, ah3, bl[ni][0], bl[ni][1]);
                mma_bf16(d[0], d[1], d[2], d[3], al0, al1, al2, al3, bh[ni][0], bh[ni][1]);
            }
        }
        s++; if (s >= 3) s -= 3;
    }

    // epilogue
    const int grp = lane >> 2;
    const int kp  = lane & 3;
#pragma unroll
    for (int mi = 0; mi < 4; mi++) {
        const int r = blockIdx.y * 128 + wm * 64 + mi * 16 + grp;
#pragma unroll
        for (int ni = 0; ni < 4; ni++) {
            const int c = blockIdx.x * 128 + wn * 32 + ni * 8 + kp * 2;
            const float b0 = bias[c], b1 = bias[c + 1];
            const float x0 = acc[mi][ni][0] + b0, x1 = acc[mi][ni][1] + b1;
            const float x2 = acc[mi][ni][2] + b0, x3 = acc[mi][ni][3] + b1;
            if (SPLIT_OUT) {
                uint32_t h0 = pack_bf16(x0, x1);
                uint32_t l0 = pack_bf16_lo(x0, x1, h0);
                uint32_t h1 = pack_bf16(x2, x3);
                uint32_t l1 = pack_bf16_lo(x2, x3, h1);
                *(uint32_t*)(Ch + (size_t)r * EMB + c)       = h0;
                *(uint32_t*)(Cl + (size_t)r * EMB + c)       = l0;
                *(uint32_t*)(Ch + (size_t)(r + 8) * EMB + c) = h1;
                *(uint32_t*)(Cl + (size_t)(r + 8) * EMB + c) = l1;
            } else {
                *(float2*)(Cf + (size_t)r * EMB + c)       = make_float2(x0, x1);
                *(float2*)(Cf + (size_t)(r + 8) * EMB + c) = make_float2(x2, x3);
            }
        }
    }
}

// ============================================================================
// Tensor-core flash attention (bf16x3) — 3-stage cp.async KV pipeline
// ============================================================================
#define BQ    64
#define BKV   64
#define KVPAD 72                         // bf16 row stride (144B)
#define KVSTG (4 * BKV * KVPAD)          // bf16 per stage (18432)
#define FLASH_SMEM (3 * KVSTG * 2)       // 110592 bytes

__global__ __launch_bounds__(128)
void flash_attn_tc_kernel(const __nv_bfloat16* __restrict__ qh_g,
                          const __nv_bfloat16* __restrict__ ql_g,
                          const __nv_bfloat16* __restrict__ kh_g,
                          const __nv_bfloat16* __restrict__ kl_g,
                          const __nv_bfloat16* __restrict__ vh_g,
                          const __nv_bfloat16* __restrict__ vl_g,
                          __nv_bfloat16* __restrict__ atth,
                          __nv_bfloat16* __restrict__ attl)
{
    extern __shared__ __nv_bfloat16 smf[];

    const int tid  = threadIdx.x;
    const int warp = tid >> 5;
    const int lane = tid & 31;
    const int grp  = lane >> 2;   // 0..7
    const int kq   = lane & 3;    // 0..3

    const int bh_i = blockIdx.y;
    const int b    = bh_i / NHEAD;
    const int h    = bh_i % NHEAD;
    const int q0   = blockIdx.x * BQ;

    const float scale = 0.125f; // 1/sqrt(64)

    const __nv_bfloat16* qh_b = qh_g + ((size_t)b * SEQ) * EMB + h * HDIM;
    const __nv_bfloat16* ql_b = ql_g + ((size_t)b * SEQ) * EMB + h * HDIM;
    const __nv_bfloat16* kh_b = kh_g + ((size_t)b * SEQ) * EMB + h * HDIM;
    const __nv_bfloat16* kl_b = kl_g + ((size_t)b * SEQ) * EMB + h * HDIM;
    const __nv_bfloat16* vh_b = vh_g + ((size_t)b * SEQ) * EMB + h * HDIM;
    const __nv_bfloat16* vl_b = vl_g + ((size_t)b * SEQ) * EMB + h * HDIM;

    const uint32_t smBase = smaddr(smf);

    // per-thread load mapping: 4 chunks of 16B per tile
    const int ldRow0 = tid >> 3;          // 0..15 (then +16 per i)
    const int ldCh   = (tid & 7) * 8;     // 0..56

    auto load_kv = [&](int s, int t0) {
        const uint32_t stage = smBase + (uint32_t)s * (KVSTG * 2);
#pragma unroll
        for (int i = 0; i < 4; i++) {
            const int row = ldRow0 + 16 * i;
            const size_t g = (size_t)(t0 + row) * EMB + ldCh;
            const uint32_t d = stage + (uint32_t)(row * KVPAD + ldCh) * 2;
            cp16(d,                     kh_b + g);
            cp16(d + BKV * KVPAD * 2,   kl_b + g);
            cp16(d + 2 * BKV * KVPAD * 2, vh_b + g);
            cp16(d + 3 * BKV * KVPAD * 2, vl_b + g);
        }
        cp_commit();
    };

    // ---- preload Q fragments (prepacked hi/lo) ----
    uint32_t qh[4][4], ql[4][4];
    {
        const int r0 = q0 + warp * 16 + grp;
#pragma unroll
        for (int kc = 0; kc < 4; kc++) {
#pragma unroll
            for (int reg = 0; reg < 4; reg++) {
                const int row = r0 + (reg & 1) * 8;
                const int col = kc * 16 + (reg >> 1) * 8 + kq * 2;
                qh[kc][reg] = *(const uint32_t*)(qh_b + (size_t)row * EMB + col);
                ql[kc][reg] = *(const uint32_t*)(ql_b + (size_t)row * EMB + col);
            }
        }
    }

    float o[8][4];
#pragma unroll
    for (int j = 0; j < 8; j++)
#pragma unroll
        for (int c = 0; c < 4; c++) o[j][c] = 0.0f;
    float m0 = -1e30f, m1 = -1e30f, l0 = 0.0f, l1 = 0.0f;

    load_kv(0, 0);
    load_kv(1, BKV);

    const int T = SEQ / BKV;   // 32
    int stg = 0;
    for (int t = 0; t < T; t++) {
        cp_wait<1>();
        __syncthreads();
        if (t + 2 < T) {
            int ns = stg + 2; if (ns >= 3) ns -= 3;
            load_kv(ns, (t + 2) * BKV);
        }

        const __nv_bfloat16* Ksh = smf + stg * KVSTG;
        const __nv_bfloat16* Ksl = Ksh + BKV * KVPAD;
        const __nv_bfloat16* Vsh = Ksh + 2 * BKV * KVPAD;
        const __nv_bfloat16* Vsl = Ksh + 3 * BKV * KVPAD;

        // ---- S = Q K^T (bf16x3) ----
        float s[8][4];
#pragma unroll
        for (int j = 0; j < 8; j++)
#pragma unroll
            for (int c = 0; c < 4; c++) s[j][c] = 0.0f;

#pragma unroll
        for (int kc = 0; kc < 4; kc++) {
#pragma unroll
            for (int j = 0; j < 8; j++) {
                const int n = j * 8 + grp;
                uint32_t kb0h = *(const uint32_t*)&Ksh[n * KVPAD + kc * 16 + kq * 2];
                uint32_t kb1h = *(const uint32_t*)&Ksh[n * KVPAD + kc * 16 + kq * 2 + 8];
                uint32_t kb0l = *(const uint32_t*)&Ksl[n * KVPAD + kc * 16 + kq * 2];
                uint32_t kb1l = *(const uint32_t*)&Ksl[n * KVPAD + kc * 16 + kq * 2 + 8];
                mma_bf16(s[j][0], s[j][1], s[j][2], s[j][3],
                         qh[kc][0], qh[kc][1], qh[kc][2], qh[kc][3], kb0h, kb1h);
                mma_bf16(s[j][0], s[j][1], s[j][2], s[j][3],
                         qh[kc][0], qh[kc][1], qh[kc][2], qh[kc][3], kb0l, kb1l);
                mma_bf16(s[j][0], s[j][1], s[j][2], s[j][3],
                         ql[kc][0], ql[kc][1], ql[kc][2], ql[kc][3], kb0h, kb1h);
            }
        }

        // ---- online softmax ----
        float mx0 = -1e30f, mx1 = -1e30f;
#pragma unroll
        for (int j = 0; j < 8; j++) {
            s[j][0] *= scale; s[j][1] *= scale; s[j][2] *= scale; s[j][3] *= scale;
            mx0 = fmaxf(mx0, fmaxf(s[j][0], s[j][1]));
            mx1 = fmaxf(mx1, fmaxf(s[j][2], s[j][3]));
        }
#pragma unroll
        for (int off = 1; off < 4; off <<= 1) {
            mx0 = fmaxf(mx0, __shfl_xor_sync(0xffffffffu, mx0, off));
            mx1 = fmaxf(mx1, __shfl_xor_sync(0xffffffffu, mx1, off));
        }
        const float mn0 = fmaxf(m0, mx0);
        const float mn1 = fmaxf(m1, mx1);
        const float corr0 = __expf(m0 - mn0);
        const float corr1 = __expf(m1 - mn1);
        float la0 = 0.0f, la1 = 0.0f;
#pragma unroll
        for (int j = 0; j < 8; j++) {
            s[j][0] = __expf(s[j][0] - mn0);
            s[j][1] = __expf(s[j][1] - mn0);
            s[j][2] = __expf(s[j][2] - mn1);
            s[j][3] = __expf(s[j][3] - mn1);
            la0 += s[j][0] + s[j][1];
            la1 += s[j][2] + s[j][3];
        }
#pragma unroll
        for (int off = 1; off < 4; off <<= 1) {
            la0 += __shfl_xor_sync(0xffffffffu, la0, off);
            la1 += __shfl_xor_sync(0xffffffffu, la1, off);
        }
        l0 = l0 * corr0 + la0;
        l1 = l1 * corr1 + la1;
        m0 = mn0; m1 = mn1;
#pragma unroll
        for (int j = 0; j < 8; j++) {
            o[j][0] *= corr0; o[j][1] *= corr0;
            o[j][2] *= corr1; o[j][3] *= corr1;
        }

        // ---- O += P V ----
#pragma unroll
        for (int kc = 0; kc < 4; kc++) {
            uint32_t ph[4], pl[4];
            ph[0] = pack_bf16(s[2*kc][0],     s[2*kc][1]);
            ph[1] = pack_bf16(s[2*kc][2],     s[2*kc][3]);
            ph[2] = pack_bf16(s[2*kc + 1][0], s[2*kc + 1][1]);
            ph[3] = pack_bf16(s[2*kc + 1][2], s[2*kc + 1][3]);
            pl[0] = pack_bf16_lo(s[2*kc][0],     s[2*kc][1],     ph[0]);
            pl[1] = pack_bf16_lo(s[2*kc][2],     s[2*kc][3],     ph[1]);
            pl[2] = pack_bf16_lo(s[2*kc + 1][0], s[2*kc + 1][1], ph[2]);
            pl[3] = pack_bf16_lo(s[2*kc + 1][2], s[2*kc + 1][3], ph[3]);

#pragma unroll
            for (int j2 = 0; j2 < 4; j2++) {
                const int vrow = kc * 16 + (lane & 15);
                const int vcol = j2 * 16 + (lane >> 4) * 8;
                uint32_t vh[4], vl[4];
                uint32_t ah = smaddr(&Vsh[vrow * KVPAD + vcol]);
                uint32_t al = smaddr(&Vsl[vrow * KVPAD + vcol]);
                asm volatile("ldmatrix.sync.aligned.m8n8.x4.trans.shared.b16 "
                             "{%0,%1,%2,%3}, [%4];"
                             : "=r"(vh[0]), "=r"(vh[1]), "=r"(vh[2]), "=r"(vh[3]) : "r"(ah));
                asm volatile("ldmatrix.sync.aligned.m8n8.x4.trans.shared.b16 "
                             "{%0,%1,%2,%3}, [%4];"
                             : "=r"(vl[0]), "=r"(vl[1]), "=r"(vl[2]), "=r"(vl[3]) : "r"(al));
                float* d0 = o[2 * j2];
                float* d1 = o[2 * j2 + 1];
                mma_bf16(d0[0], d0[1], d0[2], d0[3], ph[0], ph[1], ph[2], ph[3], vh[0], vh[1]);
                mma_bf16(d0[0], d0[1], d0[2], d0[3], ph[0], ph[1], ph[2], ph[3], vl[0], vl[1]);
                mma_bf16(d0[0], d0[1], d0[2], d0[3], pl[0], pl[1], pl[2], pl[3], vh[0], vh[1]);
                mma_bf16(d1[0], d1[1], d1[2], d1[3], ph[0], ph[1], ph[2], ph[3], vh[2], vh[3]);
                mma_bf16(d1[0], d1[1], d1[2], d1[3], ph[0], ph[1], ph[2], ph[3], vl[2], vl[3]);
                mma_bf16(d1[0], d1[1], d1[2], d1[3], pl[0], pl[1], pl[2], pl[3], vh[2], vh[3]);
            }
        }
        stg++; if (stg >= 3) stg -= 3;
    }

    // ---- epilogue: normalize + write att hi/lo at [b, n, h*64 + d] ----
    const float inv0 = 1.0f / l0;
    const float inv1 = 1.0f / l1;
    const int r0 = q0 + warp * 16 + grp;
#pragma unroll
    for (int j = 0; j < 8; j++) {
        const int col = h * HDIM + j * 8 + kq * 2;
        const float a0 = o[j][0] * inv0, a1 = o[j][1] * inv0;
        const float a2 = o[j][2] * inv1, a3 = o[j][3] * inv1;
        uint32_t h0 = pack_bf16(a0, a1);
        uint32_t l0p = pack_bf16_lo(a0, a1, h0);
        uint32_t h1 = pack_bf16(a2, a3);
        uint32_t l1p = pack_bf16_lo(a2, a3, h1);
        *(uint32_t*)(atth + ((size_t)b * SEQ + r0) * EMB + col)     = h0;
        *(uint32_t*)(attl + ((size_t)b * SEQ + r0) * EMB + col)     = l0p;
        *(uint32_t*)(atth + ((size_t)b * SEQ + r0 + 8) * EMB + col) = h1;
        *(uint32_t*)(attl + ((size_t)b * SEQ + r0 + 8) * EMB + col) = l1p;
    }
}

// ---------------- launcher ---------------------------------------------------
extern "C" void kernel_launch(void* const* d_in, const int* in_sizes, int n_in,
                              void* d_out, int out_size)
{
    const float* q  = (const float*)d_in[0];
    const float* k  = (const float*)d_in[1];
    const float* v  = (const float*)d_in[2];
    const float* Wq = (const float*)d_in[3];
    const float* bq = (const float*)d_in[4];
    const float* Wk = (const float*)d_in[5];
    const float* bk = (const float*)d_in[6];
    const float* Wv = (const float*)d_in[7];
    const float* bv = (const float*)d_in[8];
    const float* Wo = (const float*)d_in[9];
    const float* bo = (const float*)d_in[10];
    float* out = (float*)d_out;

    __nv_bfloat16 *inh, *inl, *qph, *qpl, *kph, *kpl, *vph, *vpl, *atth, *attl;
    __nv_bfloat16 *wth, *wtl;
    cudaGetSymbolAddress((void**)&inh,  g_inh);
    cudaGetSymbolAddress((void**)&inl,  g_inl);
    cudaGetSymbolAddress((void**)&qph,  g_qph);
    cudaGetSymbolAddress((void**)&qpl,  g_qpl);
    cudaGetSymbolAddress((void**)&kph,  g_kph);
    cudaGetSymbolAddress((void**)&kpl,  g_kpl);
    cudaGetSymbolAddress((void**)&vph,  g_vph);
    cudaGetSymbolAddress((void**)&vpl,  g_vpl);
    cudaGetSymbolAddress((void**)&atth, g_atth);
    cudaGetSymbolAddress((void**)&attl, g_attl);
    cudaGetSymbolAddress((void**)&wth,  g_wth);
    cudaGetSymbolAddress((void**)&wtl,  g_wtl);

    cudaFuncSetAttribute(gemm_hl_kernel<true>,
                         cudaFuncAttributeMaxDynamicSharedMemorySize, GEMM_SMEM);
    cudaFuncSetAttribute(gemm_hl_kernel<false>,
                         cudaFuncAttributeMaxDynamicSharedMemorySize, GEMM_SMEM);
    cudaFuncSetAttribute(flash_attn_tc_kernel,
                         cudaFuncAttributeMaxDynamicSharedMemorySize, FLASH_SMEM);

    // weights: split + transpose
    dim3 wgrid(EMB / 32, EMB / 32);
    dim3 wblk(32, 8);
    const float* Ws[4] = {Wq, Wk, Wv, Wo};
    for (int i = 0; i < 4; i++)
        wsplit_kernel<<<wgrid, wblk>>>(Ws[i], wth + (size_t)i * EMB * EMB,
                                       wtl + (size_t)i * EMB * EMB);

    const int sblocks = (MROWS * EMB) / 4 / 256;
    dim3 ggrid(EMB / 128, MROWS / 128);  // (8, 64)

    split_kernel<<<sblocks, 256>>>(q, inh, inl);
    gemm_hl_kernel<true><<<ggrid, 256, GEMM_SMEM>>>(inh, inl, wth, wtl, bq,
                                                    nullptr, qph, qpl);
    split_kernel<<<sblocks, 256>>>(k, inh, inl);
    gemm_hl_kernel<true><<<ggrid, 256, GEMM_SMEM>>>(inh, inl,
                                                    wth + (size_t)1 * EMB * EMB,
                                                    wtl + (size_t)1 * EMB * EMB, bk,
                                                    nullptr, kph, kpl);
    split_kernel<<<sblocks, 256>>>(v, inh, inl);
    gemm_hl_kernel<true><<<ggrid, 256, GEMM_SMEM>>>(inh, inl,
                                                    wth + (size_t)2 * EMB * EMB,
                                                    wtl + (size_t)2 * EMB * EMB, bv,
                                                    nullptr, vph, vpl);

    dim3 attn_grid(SEQ / BQ, BATCH * NHEAD); // (32, 64)
    flash_attn_tc_kernel<<<attn_grid, 128, FLASH_SMEM>>>(qph, qpl, kph, kpl,
                                                         vph, vpl, atth, attl);

    gemm_hl_kernel<false><<<ggrid, 256, GEMM_SMEM>>>(atth, attl,
                                                     wth + (size_t)3 * EMB * EMB,
                                                     wtl + (size_t)3 * EMB * EMB, bo,
                                                     out, nullptr, nullptr);
}